// round 3
// baseline (speedup 1.0000x reference)
#include <cuda_runtime.h>
#include <cstdint>

// FlowNet correlation: out[b, dy*21+dx, y, x] =
//   (1/256) * sum_c in1[b,c,y,x] * in2[b,c,y+dyo,x+dxo], dyo,dxo in {-20..20 step 2}
#define B_SZ 8
#define C_SZ 256
#define H_SZ 96
#define W_SZ 128
#define G_SZ 21

#define NWARP 7
#define NT 224
#define NCHUNK 32          // 32 chunks x 8 channels

// ---- parity-split global scratch layouts ----
// scr1 row (per b,c,y), 160 floats: even x (m=0..63 -> idx m), gap 64..79, odd x at 80+m.
// scr2 row (per b,c,yy), 208 floats, yy=0..135 (y' = yy-20; rows with y' outside [0,96) stay zero):
//   even p=2m   (m=-10..73) at idx m+10  (0..83),   pad 84..111 (never read)
//   odd  p=2m+1 (m=-10..73) at idx m+122 (112..195), pad 196..207 (never read)
#define S1_ROW 160
#define S2_ROW 208
#define S2_H 136

__device__ float scr1[(size_t)B_SZ * C_SZ * H_SZ * S1_ROW];   // 126 MB
__device__ float scr2[(size_t)B_SZ * C_SZ * S2_H * S2_ROW];   // 232 MB

// ---- shared memory (floats): [A0 | A1 | B0 | B1] ----
#define A_BUF 1280                         // 8 ch * 160
#define B_BUF (NWARP * 8 * S2_ROW)         // 56 rows * 208 = 11648
#define SMEM_FLOATS (2 * A_BUF + 2 * B_BUF)
#define SMEM_BYTES (SMEM_FLOATS * 4)       // 103424 B -> 2 blocks/SM

// ======================= pre-pass kernels =======================

__global__ void zero_scr2() {
    float4* p = (float4*)scr2;
    size_t n4 = (size_t)B_SZ * C_SZ * S2_H * S2_ROW / 4;
    for (size_t i = (size_t)blockIdx.x * blockDim.x + threadIdx.x; i < n4;
         i += (size_t)gridDim.x * blockDim.x)
        p[i] = make_float4(0.f, 0.f, 0.f, 0.f);
}

// one kernel handles both rewrites: blockIdx.y = 0 -> in1, 1 -> in2
__global__ void fill_scratch(const float* __restrict__ in1,
                             const float* __restrict__ in2) {
    int t = blockIdx.x * 256 + threadIdx.x;
    int lane = t & 31, row = t >> 5;                   // row = (b*C+c)*H + y
    if (blockIdx.y == 0) {
        float4 v = ((const float4*)in1)[(size_t)row * 32 + lane];
        float* dst = scr1 + (size_t)row * S1_ROW;
        ((float2*)dst)[lane]        = make_float2(v.x, v.z);   // even
        ((float2*)(dst + 80))[lane] = make_float2(v.y, v.w);   // odd
    } else {
        float4 v = ((const float4*)in2)[(size_t)row * 32 + lane];
        int srow = (row / H_SZ) * S2_H + (row % H_SZ) + 20;
        float* dst = scr2 + (size_t)srow * S2_ROW;
        ((float2*)dst)[lane + 5]  = make_float2(v.x, v.z);     // even -> 10+2*lane
        ((float2*)dst)[lane + 61] = make_float2(v.y, v.w);     // odd  -> 122+2*lane
    }
}

// ======================= main kernel =======================

#define CP16(dst, src) \
    asm volatile("cp.async.cg.shared.global [%0], [%1], 16;\n" ::"r"(dst), "l"(src))

__global__ __launch_bounds__(NT, 2) void corr_main(float* __restrict__ out) {
    extern __shared__ float sm[];
    const int dyt = blockIdx.x, y = blockIdx.y, b = blockIdx.z;
    const int tid = threadIdx.x, wid = tid >> 5, lane = tid & 31;
    const int pi = lane & 1, g = lane >> 1;

    // ---- copy roles: B = 56 rows x 4 segs x 13 f4 = 2912 = 224*13 cp.asyncs ----
    const int brow = tid >> 2;             // 0..55
    const int bseg = tid & 3;
    const int bw = brow >> 3, bcc = brow & 7;
    const int yy = y + 2 * (dyt * NWARP + bw);           // 0..135, always in range
    const char* gB = (const char*)(scr2 +
        ((size_t)((b * C_SZ + bcc) * S2_H + yy)) * S2_ROW + bseg * 52);
    const size_t gBstep = (size_t)8 * S2_H * S2_ROW * 4; // bytes per chunk
    // A: threads 0..71, 4 f4 each (8 ch x 9 segs of 16 floats = idx 0..143)
    const int acc9 = tid / 9, aq = tid - acc9 * 9;
    const char* gA = (const char*)(scr1 +
        ((size_t)((b * C_SZ + acc9) * H_SZ + y)) * S1_ROW + aq * 16);
    const size_t gAstep = (size_t)8 * H_SZ * S1_ROW * 4;

    const uint32_t smbase = (uint32_t)__cvta_generic_to_shared(sm);
    const uint32_t dA[2] = {smbase + (uint32_t)(acc9 * S1_ROW + aq * 16) * 4,
                            smbase + A_BUF * 4 + (uint32_t)(acc9 * S1_ROW + aq * 16) * 4};
    const uint32_t dB[2] = {smbase + 2 * A_BUF * 4 + (uint32_t)(brow * S2_ROW + bseg * 52) * 4,
                            smbase + (2 * A_BUF + B_BUF) * 4 + (uint32_t)(brow * S2_ROW + bseg * 52) * 4};

    // ---- consumer offsets ----
    const int aoff = pi * 80 + 4 * g;
    const int boff = wid * 8 * S2_ROW + pi * 112 + 4 * g;
    const float* Ap[2] = {sm + aoff, sm + A_BUF + aoff};
    const float* Bp[2] = {sm + 2 * A_BUF + boff, sm + 2 * A_BUF + B_BUF + boff};

    float acc[4][21];
#pragma unroll
    for (int r = 0; r < 4; ++r)
#pragma unroll
        for (int d = 0; d < 21; ++d) acc[r][d] = 0.0f;

#define ISSUE(ch, buf)                                                        \
    do {                                                                      \
        const char* gs = gB + (size_t)(ch) * gBstep;                          \
        _Pragma("unroll") for (int j = 0; j < 13; ++j)                        \
            CP16(dB[buf] + j * 16, gs + j * 16);                              \
        if (tid < 72) {                                                       \
            const char* ga = gA + (size_t)(ch) * gAstep;                      \
            _Pragma("unroll") for (int j = 0; j < 4; ++j)                     \
                CP16(dA[buf] + j * 16, ga + j * 16);                          \
        }                                                                     \
    } while (0)

    ISSUE(0, 0);
    asm volatile("cp.async.commit_group;\n");

#pragma unroll 1
    for (int ch = 0; ch < NCHUNK; ++ch) {
        const int cb = ch & 1;
        if (ch + 1 < NCHUNK) ISSUE(ch + 1, cb ^ 1);
        asm volatile("cp.async.commit_group;\n");
        asm volatile("cp.async.wait_group 1;\n");
        __syncthreads();

        const float* ap = Ap[cb];
        const float* bp = Bp[cb];
#pragma unroll
        for (int cc = 0; cc < 8; ++cc) {
            float4 av = *(const float4*)(ap + cc * S1_ROW);
            float wv[24];
#pragma unroll
            for (int j = 0; j < 6; ++j) {
                float4 tv = *(const float4*)(bp + cc * S2_ROW + 4 * j);
                wv[4 * j] = tv.x; wv[4 * j + 1] = tv.y;
                wv[4 * j + 2] = tv.z; wv[4 * j + 3] = tv.w;
            }
#pragma unroll
            for (int d = 0; d < 21; ++d) {
                acc[0][d] = fmaf(av.x, wv[d + 0], acc[0][d]);
                acc[1][d] = fmaf(av.y, wv[d + 1], acc[1][d]);
                acc[2][d] = fmaf(av.z, wv[d + 2], acc[2][d]);
                acc[3][d] = fmaf(av.w, wv[d + 3], acc[3][d]);
            }
        }
        __syncthreads();
    }

    // ---- epilogue: per-warp smem staging -> coalesced float4 stores ----
    float* stage = sm + wid * 128;           // reuses A0 (no longer needed)
    const float inv = 1.0f / 256.0f;
    const int xb = 8 * g + pi;
    float4* outf4 = (float4*)out;
    const int dy_idx = dyt * NWARP + wid;
    const int dbase = b * (G_SZ * G_SZ) + dy_idx * G_SZ;

#pragma unroll 1
    for (int d = 0; d < 21; ++d) {
        __syncwarp();
        stage[xb + 0] = acc[0][d] * inv;
        stage[xb + 2] = acc[1][d] * inv;
        stage[xb + 4] = acc[2][d] * inv;
        stage[xb + 6] = acc[3][d] * inv;
        __syncwarp();
        outf4[(size_t)((dbase + d) * H_SZ + y) * (W_SZ / 4) + lane] =
            ((const float4*)stage)[lane];
    }
}

// ======================= launch =======================

extern "C" void kernel_launch(void* const* d_in, const int* in_sizes, int n_in,
                              void* d_out, int out_size) {
    const float* in1 = (const float*)d_in[0];
    const float* in2 = (const float*)d_in[1];
    float* out = (float*)d_out;

    cudaFuncSetAttribute(corr_main, cudaFuncAttributeMaxDynamicSharedMemorySize,
                         SMEM_BYTES);

    zero_scr2<<<4096, 256>>>();
    {
        int rows = B_SZ * C_SZ * H_SZ;                 // 196608
        dim3 fg(rows * 32 / 256, 2);                   // (24576, 2)
        fill_scratch<<<fg, 256>>>(in1, in2);
    }

    dim3 grid(3, H_SZ, B_SZ);                          // 2304 blocks
    corr_main<<<grid, NT, SMEM_BYTES>>>(out);
}